// round 12
// baseline (speedup 1.0000x reference)
#include <cuda_runtime.h>

// Problem-fixed shapes
#define NN 50000
#define EE 800000
#define TT (EE + NN)      // real edges + self loops
#define H1 3
#define D1 192            // 3 heads x 64
#define D2 64
#define NG 128
#define NBLK ((NN + 255) / 256)   // 196 scan blocks
#define NSPLIT 25024              // agg1/gemm2 pipeline split (mult of 8 and 64)

// ---------------- scratch (device globals; no runtime allocation) -----------
__device__ float g_xp1[(size_t)NN * D1];   // layer1 lin output
__device__ float g_h1[(size_t)NN * D1];    // elu(agg + b1)
__device__ float g_asrc1v[(size_t)NN * 4]; // float4-padded src logits (3 heads + pad)
__device__ float g_adst1[NN * H1];
__device__ float g_xp2[(size_t)NN * D2];
__device__ float g_asrc2[NN];
__device__ float g_adst2[NN];
__device__ float g_pool[NG * D2];
__device__ float g_cnt[NG];
__device__ float g_u_src[H1 * 128];        // W1^T @ att_src per head
__device__ float g_u_dst[H1 * 128];        // W1^T @ att_dst per head
// CSR (rebuilt every call; deterministic content, order-free use)
__device__ int   g_deg[NN];        // degree, then reused as scatter cursor
__device__ int   g_row[NN + 1];    // row offsets
__device__ int   g_csrc[TT];       // src node per CSR slot
__device__ int   g_bsum[NBLK];     // per-block degree sums
__device__ int   g_boff[NBLK];     // exclusive block offsets

// ---------------- helpers ----------------------------------------------------
__device__ __forceinline__ float warp_sum(float s) {
    #pragma unroll
    for (int o = 16; o; o >>= 1) s += __shfl_xor_sync(0xFFFFFFFFu, s, o);
    return s;
}
__device__ __forceinline__ float lrelu(float a) { return fmaxf(a, 0.2f * a); }
__device__ __forceinline__ unsigned long long pk2(float lo, float hi) {
    unsigned long long r;
    asm("mov.b64 %0, {%1, %2};" : "=l"(r) : "f"(lo), "f"(hi));
    return r;
}
__device__ __forceinline__ void upk2(float& lo, float& hi, unsigned long long v) {
    asm("mov.b64 {%0, %1}, %2;" : "=f"(lo), "=f"(hi) : "l"(v));
}
__device__ __forceinline__ void fma2(unsigned long long& acc, unsigned long long a,
                                     unsigned long long b) {
    asm("fma.rn.f32x2 %0, %1, %2, %0;" : "+l"(acc) : "l"(a), "l"(b));
}

// ---------------- init (merged) -----------------------------------------------
__global__ void k_init() {
    int i = blockIdx.x * blockDim.x + threadIdx.x;
    if (i < NN) g_deg[i] = 1;            // self loop
    if (i < NG * D2) g_pool[i] = 0.f;
    if (i < NG) g_cnt[i] = 0.f;
}

// ---------------- u = W1^T @ att  (block = head, 128 threads = k) -------------
__global__ void k_prep_u(const float* __restrict__ W1, const float* __restrict__ attS,
                         const float* __restrict__ attD) {
    int h = blockIdx.x, k = threadIdx.x;
    const float* wr = W1 + (size_t)k * 192 + h * 64;
    const float* as = attS + h * 64;
    const float* ad = attD + h * 64;
    float us = 0.f, ud = 0.f;
    #pragma unroll 8
    for (int c = 0; c < 64; c++) {
        float w = wr[c];
        us = fmaf(w, as[c], us);
        ud = fmaf(w, ad[c], ud);
    }
    g_u_src[h * 128 + k] = us;
    g_u_dst[h * 128 + k] = ud;
}

// ---------------- layer1 attention dots directly from x (warp per node) -------
__global__ void k_att1x(const float* __restrict__ x) {
    int n = blockIdx.x * 8 + (threadIdx.x >> 5);
    if (n >= NN) return;
    int lane = threadIdx.x & 31;
    const float* xr = x + (size_t)n * 128;
    float x0 = __ldg(xr + lane),      x1 = __ldg(xr + lane + 32);
    float x2 = __ldg(xr + lane + 64), x3 = __ldg(xr + lane + 96);
    #pragma unroll
    for (int h = 0; h < 3; h++) {
        const float* us = g_u_src + h * 128;
        const float* ud = g_u_dst + h * 128;
        float ss = x0 * us[lane] + x1 * us[lane + 32] + x2 * us[lane + 64] + x3 * us[lane + 96];
        float sd = x0 * ud[lane] + x1 * ud[lane + 32] + x2 * ud[lane + 64] + x3 * ud[lane + 96];
        ss = warp_sum(ss); sd = warp_sum(sd);
        if (lane == 0) { g_asrc1v[(size_t)n * 4 + h] = ss; g_adst1[n * 3 + h] = sd; }
    }
}

// ---------------- CSR build ---------------------------------------------------
__global__ void k_hist(const int* __restrict__ dstp, int E) {
    int e = blockIdx.x * blockDim.x + threadIdx.x;
    if (e < E) atomicAdd(&g_deg[__ldg(dstp + e)], 1);
}

__global__ void k_scan_blk() {
    __shared__ int sd[256];
    int t = threadIdx.x;
    int i = blockIdx.x * 256 + t;
    int v = (i < NN) ? g_deg[i] : 0;
    sd[t] = v;
    __syncthreads();
    #pragma unroll
    for (int off = 1; off < 256; off <<= 1) {
        int u = (t >= off) ? sd[t - off] : 0;
        __syncthreads();
        sd[t] += u;
        __syncthreads();
    }
    if (i < NN) g_row[i] = sd[t] - v;
    if (t == 255) g_bsum[blockIdx.x] = sd[255];
}

__global__ void k_scan_top() {
    __shared__ int sd[256];
    int t = threadIdx.x;
    int v = (t < NBLK) ? g_bsum[t] : 0;
    sd[t] = v;
    __syncthreads();
    #pragma unroll
    for (int off = 1; off < 256; off <<= 1) {
        int u = (t >= off) ? sd[t - off] : 0;
        __syncthreads();
        sd[t] += u;
        __syncthreads();
    }
    if (t < NBLK) g_boff[t] = sd[t] - v;
    if (t == 255) g_row[NN] = sd[255];
}

__global__ void k_csr_fin() {
    int i = blockIdx.x * 256 + threadIdx.x;
    if (i >= NN) return;
    int r = g_row[i] + g_boff[blockIdx.x];
    g_row[i] = r;
    g_csrc[r] = i;          // self-loop slot
    g_deg[i] = r + 1;       // scatter cursor starts after self loop
}

__global__ void k_scatter(const int* __restrict__ srcp, const int* __restrict__ dstp, int E) {
    int e = blockIdx.x * blockDim.x + threadIdx.x;
    if (e >= E) return;
    int pos = atomicAdd(&g_deg[__ldg(dstp + e)], 1);
    g_csrc[pos] = __ldg(srcp + e);
}

// ---------------- GEMM1: xp1 = x @ W1  (64x64 tile, both operands in smem) ---
__global__ void k_gemm1(const float* __restrict__ x, const float* __restrict__ W1) {
    __shared__ float xs[64][72];
    __shared__ float ws[64][68];
    int t = threadIdx.x;           // 0..127
    int r0 = blockIdx.x * 64;
    int c0 = blockIdx.y * 64;
    int tr = t >> 4;               // rows [tr*8, tr*8+8)
    int tc = t & 15;               // cols [tc*4, tc*4+4)
    unsigned long long acc[4][4];
    #pragma unroll
    for (int p = 0; p < 4; p++)
        #pragma unroll
        for (int j = 0; j < 4; j++) acc[p][j] = 0ull;

    for (int k0 = 0; k0 < 128; k0 += 64) {
        __syncthreads();
        for (int i = t; i < 64 * 64; i += 128) {
            int c = i & 63, r = i >> 6;
            xs[c][r] = (r0 + r < NN) ? x[(size_t)(r0 + r) * 128 + k0 + c] : 0.f;
        }
        for (int i = t; i < 64 * 64; i += 128) {
            int c = i & 63, k = i >> 6;
            ws[k][c] = W1[(k0 + k) * 192 + c0 + c];
        }
        __syncthreads();
        #pragma unroll 4
        for (int kk = 0; kk < 64; kk++) {
            float4 wv = *(const float4*)&ws[kk][tc * 4];
            unsigned long long w0 = pk2(wv.x, wv.x), w1 = pk2(wv.y, wv.y);
            unsigned long long w2 = pk2(wv.z, wv.z), w3 = pk2(wv.w, wv.w);
            const ulonglong2* xp = (const ulonglong2*)&xs[kk][tr * 8];
            ulonglong2 q0 = xp[0], q1 = xp[1];
            fma2(acc[0][0], q0.x, w0); fma2(acc[0][1], q0.x, w1);
            fma2(acc[0][2], q0.x, w2); fma2(acc[0][3], q0.x, w3);
            fma2(acc[1][0], q0.y, w0); fma2(acc[1][1], q0.y, w1);
            fma2(acc[1][2], q0.y, w2); fma2(acc[1][3], q0.y, w3);
            fma2(acc[2][0], q1.x, w0); fma2(acc[2][1], q1.x, w1);
            fma2(acc[2][2], q1.x, w2); fma2(acc[2][3], q1.x, w3);
            fma2(acc[3][0], q1.y, w0); fma2(acc[3][1], q1.y, w1);
            fma2(acc[3][2], q1.y, w2); fma2(acc[3][3], q1.y, w3);
        }
    }
    #pragma unroll
    for (int p = 0; p < 4; p++) {
        float lo0, hi0, lo1, hi1, lo2, hi2, lo3, hi3;
        upk2(lo0, hi0, acc[p][0]); upk2(lo1, hi1, acc[p][1]);
        upk2(lo2, hi2, acc[p][2]); upk2(lo3, hi3, acc[p][3]);
        int r = r0 + tr * 8 + 2 * p;
        if (r < NN)
            *(float4*)&g_xp1[(size_t)r * 192 + c0 + tc * 4] = make_float4(lo0, lo1, lo2, lo3);
        if (r + 1 < NN)
            *(float4*)&g_xp1[(size_t)(r + 1) * 192 + c0 + tc * 4] = make_float4(hi0, hi1, hi2, hi3);
    }
}

// ---------------- fused layer1 (node range [n0,n1)) ---------------------------
__global__ void k_agg1(const float* __restrict__ b1, int n0, int n1) {
    int d = n0 + blockIdx.x * 8 + (threadIdx.x >> 5);
    if (d >= n1) return;
    int lane = threadIdx.x & 31;
    float ad0 = g_adst1[d * 3 + 0], ad1 = g_adst1[d * 3 + 1], ad2 = g_adst1[d * 3 + 2];
    float acc0 = 0.f, acc1 = 0.f, acc2 = 0.f, acc3 = 0.f, acc4 = 0.f, acc5 = 0.f;
    float den0 = 0.f, den1 = 0.f, den2 = 0.f;
    int beg = g_row[d], end = g_row[d + 1];
    int j = beg;
    for (; j + 2 <= end; j += 2) {
        int s0 = __ldg(g_csrc + j), s1 = __ldg(g_csrc + j + 1);
        float4 av0 = __ldg((const float4*)g_asrc1v + s0);
        float4 av1 = __ldg((const float4*)g_asrc1v + s1);
        const float* x0 = g_xp1 + (size_t)s0 * 192 + lane;
        const float* x1 = g_xp1 + (size_t)s1 * 192 + lane;
        float f00 = __ldg(x0),       f01 = __ldg(x0 + 32),  f02 = __ldg(x0 + 64);
        float f03 = __ldg(x0 + 96),  f04 = __ldg(x0 + 128), f05 = __ldg(x0 + 160);
        float f10 = __ldg(x1),       f11 = __ldg(x1 + 32),  f12 = __ldg(x1 + 64);
        float f13 = __ldg(x1 + 96),  f14 = __ldg(x1 + 128), f15 = __ldg(x1 + 160);
        float e00 = __expf(lrelu(av0.x + ad0));
        float e01 = __expf(lrelu(av0.y + ad1));
        float e02 = __expf(lrelu(av0.z + ad2));
        float e10 = __expf(lrelu(av1.x + ad0));
        float e11 = __expf(lrelu(av1.y + ad1));
        float e12 = __expf(lrelu(av1.z + ad2));
        den0 += e00 + e10; den1 += e01 + e11; den2 += e02 + e12;
        acc0 = fmaf(e00, f00, acc0); acc1 = fmaf(e00, f01, acc1);
        acc2 = fmaf(e01, f02, acc2); acc3 = fmaf(e01, f03, acc3);
        acc4 = fmaf(e02, f04, acc4); acc5 = fmaf(e02, f05, acc5);
        acc0 = fmaf(e10, f10, acc0); acc1 = fmaf(e10, f11, acc1);
        acc2 = fmaf(e11, f12, acc2); acc3 = fmaf(e11, f13, acc3);
        acc4 = fmaf(e12, f14, acc4); acc5 = fmaf(e12, f15, acc5);
    }
    if (j < end) {
        int s = __ldg(g_csrc + j);
        float4 av = __ldg((const float4*)g_asrc1v + s);
        const float* xr = g_xp1 + (size_t)s * 192 + lane;
        float e0 = __expf(lrelu(av.x + ad0));
        float e1 = __expf(lrelu(av.y + ad1));
        float e2 = __expf(lrelu(av.z + ad2));
        den0 += e0; den1 += e1; den2 += e2;
        acc0 = fmaf(e0, __ldg(xr),       acc0);
        acc1 = fmaf(e0, __ldg(xr + 32),  acc1);
        acc2 = fmaf(e1, __ldg(xr + 64),  acc2);
        acc3 = fmaf(e1, __ldg(xr + 96),  acc3);
        acc4 = fmaf(e2, __ldg(xr + 128), acc4);
        acc5 = fmaf(e2, __ldg(xr + 160), acc5);
    }
    float i0 = 1.f / fmaxf(den0, 1e-16f);
    float i1 = 1.f / fmaxf(den1, 1e-16f);
    float i2 = 1.f / fmaxf(den2, 1e-16f);
    float* o = g_h1 + (size_t)d * 192 + lane;
    float v;
    v = acc0 * i0 + b1[lane];       o[0]   = v > 0.f ? v : expm1f(v);
    v = acc1 * i0 + b1[lane + 32];  o[32]  = v > 0.f ? v : expm1f(v);
    v = acc2 * i1 + b1[lane + 64];  o[64]  = v > 0.f ? v : expm1f(v);
    v = acc3 * i1 + b1[lane + 96];  o[96]  = v > 0.f ? v : expm1f(v);
    v = acc4 * i2 + b1[lane + 128]; o[128] = v > 0.f ? v : expm1f(v);
    v = acc5 * i2 + b1[lane + 160]; o[160] = v > 0.f ? v : expm1f(v);
}

// ---------------- GEMM2 + fused att2 epilogue (row range from base) -----------
// Tile is full-N (64 cols), so each row's attention dots reduce across the 16
// contiguous lanes holding that row (width-16 shuffle).
__global__ void k_gemm2(const float* __restrict__ W2, const float* __restrict__ as2,
                        const float* __restrict__ ad2v, int base) {
    __shared__ float xs[64][72];
    __shared__ float ws[64][68];
    int t = threadIdx.x;
    int r0 = base + blockIdx.x * 64;
    int tr = t >> 4;
    int tc = t & 15;
    unsigned long long acc[4][4];
    #pragma unroll
    for (int p = 0; p < 4; p++)
        #pragma unroll
        for (int j = 0; j < 4; j++) acc[p][j] = 0ull;

    for (int k0 = 0; k0 < 192; k0 += 64) {
        __syncthreads();
        for (int i = t; i < 64 * 64; i += 128) {
            int c = i & 63, r = i >> 6;
            xs[c][r] = (r0 + r < NN) ? g_h1[(size_t)(r0 + r) * 192 + k0 + c] : 0.f;
        }
        for (int i = t; i < 64 * 64; i += 128) {
            int c = i & 63, k = i >> 6;
            ws[k][c] = W2[(k0 + k) * 64 + c];
        }
        __syncthreads();
        #pragma unroll 4
        for (int kk = 0; kk < 64; kk++) {
            float4 wv = *(const float4*)&ws[kk][tc * 4];
            unsigned long long w0 = pk2(wv.x, wv.x), w1 = pk2(wv.y, wv.y);
            unsigned long long w2 = pk2(wv.z, wv.z), w3 = pk2(wv.w, wv.w);
            const ulonglong2* xp = (const ulonglong2*)&xs[kk][tr * 8];
            ulonglong2 q0 = xp[0], q1 = xp[1];
            fma2(acc[0][0], q0.x, w0); fma2(acc[0][1], q0.x, w1);
            fma2(acc[0][2], q0.x, w2); fma2(acc[0][3], q0.x, w3);
            fma2(acc[1][0], q0.y, w0); fma2(acc[1][1], q0.y, w1);
            fma2(acc[1][2], q0.y, w2); fma2(acc[1][3], q0.y, w3);
            fma2(acc[2][0], q1.x, w0); fma2(acc[2][1], q1.x, w1);
            fma2(acc[2][2], q1.x, w2); fma2(acc[2][3], q1.x, w3);
            fma2(acc[3][0], q1.y, w0); fma2(acc[3][1], q1.y, w1);
            fma2(acc[3][2], q1.y, w2); fma2(acc[3][3], q1.y, w3);
        }
    }

    float4 a_s = *(const float4*)&as2[tc * 4];
    float4 a_d = *(const float4*)&ad2v[tc * 4];
    #pragma unroll
    for (int p = 0; p < 4; p++) {
        float lo0, hi0, lo1, hi1, lo2, hi2, lo3, hi3;
        upk2(lo0, hi0, acc[p][0]); upk2(lo1, hi1, acc[p][1]);
        upk2(lo2, hi2, acc[p][2]); upk2(lo3, hi3, acc[p][3]);
        int r = r0 + tr * 8 + 2 * p;
        // row r (lo) and row r+1 (hi): partial attention dots over this thread's 4 cols
        float psL = lo0 * a_s.x + lo1 * a_s.y + lo2 * a_s.z + lo3 * a_s.w;
        float pdL = lo0 * a_d.x + lo1 * a_d.y + lo2 * a_d.z + lo3 * a_d.w;
        float psH = hi0 * a_s.x + hi1 * a_s.y + hi2 * a_s.z + hi3 * a_s.w;
        float pdH = hi0 * a_d.x + hi1 * a_d.y + hi2 * a_d.z + hi3 * a_d.w;
        #pragma unroll
        for (int off = 8; off; off >>= 1) {
            psL += __shfl_xor_sync(0xFFFFFFFFu, psL, off, 16);
            pdL += __shfl_xor_sync(0xFFFFFFFFu, pdL, off, 16);
            psH += __shfl_xor_sync(0xFFFFFFFFu, psH, off, 16);
            pdH += __shfl_xor_sync(0xFFFFFFFFu, pdH, off, 16);
        }
        if (r < NN) {
            *(float4*)&g_xp2[(size_t)r * 64 + tc * 4] = make_float4(lo0, lo1, lo2, lo3);
            if (tc == 0) { g_asrc2[r] = psL; g_adst2[r] = pdL; }
        }
        if (r + 1 < NN) {
            *(float4*)&g_xp2[(size_t)(r + 1) * 64 + tc * 4] = make_float4(hi0, hi1, hi2, hi3);
            if (tc == 0) { g_asrc2[r + 1] = psH; g_adst2[r + 1] = pdH; }
        }
    }
}

// ---------------- fused layer2: softmax + aggregate + bias + pool -------------
__global__ void k_agg2(const float* __restrict__ b2, const int* __restrict__ batch) {
    int d = blockIdx.x * 8 + (threadIdx.x >> 5);
    if (d >= NN) return;
    int lane = threadIdx.x & 31;
    float ad = g_adst2[d];
    float acc0 = 0.f, acc1 = 0.f, den = 0.f;
    int beg = g_row[d], end = g_row[d + 1];
    int j = beg;
    for (; j + 2 <= end; j += 2) {
        int s0 = __ldg(g_csrc + j), s1 = __ldg(g_csrc + j + 1);
        float a0 = __ldg(g_asrc2 + s0), a1 = __ldg(g_asrc2 + s1);
        const float* x0 = g_xp2 + (size_t)s0 * 64 + lane;
        const float* x1 = g_xp2 + (size_t)s1 * 64 + lane;
        float f00 = __ldg(x0), f01 = __ldg(x0 + 32);
        float f10 = __ldg(x1), f11 = __ldg(x1 + 32);
        float e0 = __expf(lrelu(a0 + ad));
        float e1 = __expf(lrelu(a1 + ad));
        den += e0 + e1;
        acc0 = fmaf(e0, f00, acc0); acc1 = fmaf(e0, f01, acc1);
        acc0 = fmaf(e1, f10, acc0); acc1 = fmaf(e1, f11, acc1);
    }
    if (j < end) {
        int s = __ldg(g_csrc + j);
        float e = __expf(lrelu(__ldg(g_asrc2 + s) + ad));
        den += e;
        const float* xr = g_xp2 + (size_t)s * 64 + lane;
        acc0 = fmaf(e, __ldg(xr),      acc0);
        acc1 = fmaf(e, __ldg(xr + 32), acc1);
    }
    float inv = 1.f / fmaxf(den, 1e-16f);
    int b = __ldg(batch + d);
    atomicAdd(&g_pool[b * 64 + lane],      acc0 * inv + b2[lane]);
    atomicAdd(&g_pool[b * 64 + lane + 32], acc1 * inv + b2[lane + 32]);
    if (lane == 0) atomicAdd(&g_cnt[b], 1.0f);
}

// ---------------- final: (pool/cnt) @ lin_W + lin_b ---------------------------
__global__ void k_final(const float* __restrict__ lin_W, const float* __restrict__ lin_b,
                        float* __restrict__ out) {
    int t = blockIdx.x * blockDim.x + threadIdx.x;
    if (t >= NG * 10) return;
    int g = t / 10, j = t % 10;
    float inv = 1.0f / fmaxf(g_cnt[g], 1.0f);
    float acc = lin_b[j];
    #pragma unroll 8
    for (int c = 0; c < 64; c++)
        acc += g_pool[g * 64 + c] * inv * lin_W[c * 10 + j];
    out[t] = acc;
}

// ---------------- host launch -------------------------------------------------
extern "C" void kernel_launch(void* const* d_in, const int* in_sizes, int n_in,
                              void* d_out, int out_size) {
    const float* x        = (const float*)d_in[0];
    const int*   ei       = (const int*)  d_in[1];
    const int*   batch    = (const int*)  d_in[2];
    const float* W1       = (const float*)d_in[3];
    const float* att_src1 = (const float*)d_in[4];
    const float* att_dst1 = (const float*)d_in[5];
    const float* b1       = (const float*)d_in[6];
    const float* W2       = (const float*)d_in[7];
    const float* att_src2 = (const float*)d_in[8];
    const float* att_dst2 = (const float*)d_in[9];
    const float* b2       = (const float*)d_in[10];
    const float* lin_W    = (const float*)d_in[11];
    const float* lin_b    = (const float*)d_in[12];
    float* out = (float*)d_out;

    int E = in_sizes[1] / 2;            // 800000
    const int* srcp = ei;
    const int* dstp = ei + E;

    cudaStream_t s1;
    cudaStreamCreate(&s1);
    cudaEvent_t evF, evJ, evA, evB;
    cudaEventCreateWithFlags(&evF, cudaEventDisableTiming);
    cudaEventCreateWithFlags(&evJ, cudaEventDisableTiming);
    cudaEventCreateWithFlags(&evA, cudaEventDisableTiming);
    cudaEventCreateWithFlags(&evB, cudaEventDisableTiming);

    k_init<<<(NN + 255) / 256, 256>>>();                        // L0 (s0)
    cudaEventRecord(evF, 0);
    cudaStreamWaitEvent(s1, evF, 0);

    k_prep_u<<<3, 128, 0, s1>>>(W1, att_src1, att_dst1);        // L1 (s1)
    k_hist<<<(E + 255) / 256, 256, 0, s1>>>(dstp, E);           // L2 (s1)
    k_gemm1<<<dim3((NN + 63) / 64, 3), 128>>>(x, W1);           // L3 (s0) PROFILED
    k_att1x<<<(NN + 7) / 8, 256, 0, s1>>>(x);                   // L4 (s1)
    k_scan_blk<<<NBLK, 256, 0, s1>>>();                         // L5 (s1)
    k_scan_top<<<1, 256, 0, s1>>>();                            // L6 (s1)
    k_csr_fin<<<NBLK, 256, 0, s1>>>();                          // L7 (s1)
    k_scatter<<<(E + 255) / 256, 256, 0, s1>>>(srcp, dstp, E);  // L8 (s1)

    cudaEventRecord(evJ, s1);
    cudaStreamWaitEvent(0, evJ, 0);

    // agg1/gemm2 pipeline: s0: agg1_A -> gemm2_A ; s1: (after agg1_A) agg1_B -> gemm2_B
    k_agg1<<<NSPLIT / 8, 256>>>(b1, 0, NSPLIT);
    cudaEventRecord(evA, 0);
    cudaStreamWaitEvent(s1, evA, 0);
    k_agg1<<<(NN - NSPLIT + 7) / 8, 256, 0, s1>>>(b1, NSPLIT, NN);
    k_gemm2<<<NSPLIT / 64, 128>>>(W2, att_src2, att_dst2, 0);
    k_gemm2<<<(NN - NSPLIT + 63) / 64, 128, 0, s1>>>(W2, att_src2, att_dst2, NSPLIT);
    cudaEventRecord(evB, s1);
    cudaStreamWaitEvent(0, evB, 0);

    // layer 2 aggregation + pooling, then readout
    k_agg2<<<(NN + 7) / 8, 256>>>(b2, batch);
    k_final<<<10, 128>>>(lin_W, lin_b, out);

    cudaEventDestroy(evF);
    cudaEventDestroy(evJ);
    cudaEventDestroy(evA);
    cudaEventDestroy(evB);
    cudaStreamDestroy(s1);
}

// round 13
// speedup vs baseline: 1.1067x; 1.1067x over previous
#include <cuda_runtime.h>

// Problem-fixed shapes
#define NN 50000
#define EE 800000
#define TT (EE + NN)      // real edges + self loops
#define H1 3
#define D1 192            // 3 heads x 64
#define D2 64
#define NG 128
#define NBLK ((NN + 255) / 256)   // 196 scan blocks

// ---------------- scratch (device globals; no runtime allocation) -----------
__device__ float g_xp1[(size_t)NN * D1];   // layer1 lin output
__device__ float g_h1[(size_t)NN * D1];    // elu(agg + b1)
__device__ float g_asrc1v[(size_t)NN * 4]; // float4-padded src logits (3 heads + pad)
__device__ float g_adst1[NN * H1];
__device__ float g_xp2[(size_t)NN * D2];
__device__ float g_asrc2[NN];
__device__ float g_adst2[NN];
__device__ float g_pool[NG * D2];
__device__ float g_cnt[NG];
__device__ float g_u_src[H1 * 128];        // W1^T @ att_src per head
__device__ float g_u_dst[H1 * 128];        // W1^T @ att_dst per head
// CSR (rebuilt every call; deterministic content, order-free use)
__device__ int   g_deg[NN];        // degree, then reused as scatter cursor
__device__ int   g_row[NN + 1];    // row offsets
__device__ int   g_csrc[TT];       // src node per CSR slot
__device__ int   g_bsum[NBLK];     // per-block degree sums
__device__ int   g_boff[NBLK];     // exclusive block offsets

// ---------------- helpers ----------------------------------------------------
__device__ __forceinline__ float warp_sum(float s) {
    #pragma unroll
    for (int o = 16; o; o >>= 1) s += __shfl_xor_sync(0xFFFFFFFFu, s, o);
    return s;
}
__device__ __forceinline__ float lrelu(float a) { return fmaxf(a, 0.2f * a); }
__device__ __forceinline__ unsigned long long pk2(float lo, float hi) {
    unsigned long long r;
    asm("mov.b64 %0, {%1, %2};" : "=l"(r) : "f"(lo), "f"(hi));
    return r;
}
__device__ __forceinline__ void upk2(float& lo, float& hi, unsigned long long v) {
    asm("mov.b64 {%0, %1}, %2;" : "=f"(lo), "=f"(hi) : "l"(v));
}
__device__ __forceinline__ void fma2(unsigned long long& acc, unsigned long long a,
                                     unsigned long long b) {
    asm("fma.rn.f32x2 %0, %1, %2, %0;" : "+l"(acc) : "l"(a), "l"(b));
}

// ---------------- init (merged) -----------------------------------------------
__global__ void k_init() {
    int i = blockIdx.x * blockDim.x + threadIdx.x;
    if (i < NN) g_deg[i] = 1;            // self loop
    if (i < NG * D2) g_pool[i] = 0.f;
    if (i < NG) g_cnt[i] = 0.f;
}

// ---------------- u = W1^T @ att  (block = head, 128 threads = k) -------------
__global__ void k_prep_u(const float* __restrict__ W1, const float* __restrict__ attS,
                         const float* __restrict__ attD) {
    int h = blockIdx.x, k = threadIdx.x;
    const float* wr = W1 + (size_t)k * 192 + h * 64;
    const float* as = attS + h * 64;
    const float* ad = attD + h * 64;
    float us = 0.f, ud = 0.f;
    #pragma unroll 8
    for (int c = 0; c < 64; c++) {
        float w = wr[c];
        us = fmaf(w, as[c], us);
        ud = fmaf(w, ad[c], ud);
    }
    g_u_src[h * 128 + k] = us;
    g_u_dst[h * 128 + k] = ud;
}

// ---------------- layer1 attention dots directly from x (warp per node) -------
__global__ void k_att1x(const float* __restrict__ x) {
    int n = blockIdx.x * 8 + (threadIdx.x >> 5);
    if (n >= NN) return;
    int lane = threadIdx.x & 31;
    const float* xr = x + (size_t)n * 128;
    float x0 = __ldg(xr + lane),      x1 = __ldg(xr + lane + 32);
    float x2 = __ldg(xr + lane + 64), x3 = __ldg(xr + lane + 96);
    #pragma unroll
    for (int h = 0; h < 3; h++) {
        const float* us = g_u_src + h * 128;
        const float* ud = g_u_dst + h * 128;
        float ss = x0 * us[lane] + x1 * us[lane + 32] + x2 * us[lane + 64] + x3 * us[lane + 96];
        float sd = x0 * ud[lane] + x1 * ud[lane + 32] + x2 * ud[lane + 64] + x3 * ud[lane + 96];
        ss = warp_sum(ss); sd = warp_sum(sd);
        if (lane == 0) { g_asrc1v[(size_t)n * 4 + h] = ss; g_adst1[n * 3 + h] = sd; }
    }
}

// ---------------- CSR build ---------------------------------------------------
__global__ void k_hist(const int* __restrict__ dstp, int E) {
    int e = blockIdx.x * blockDim.x + threadIdx.x;
    if (e < E) atomicAdd(&g_deg[__ldg(dstp + e)], 1);
}

__global__ void k_scan_blk() {
    __shared__ int sd[256];
    int t = threadIdx.x;
    int i = blockIdx.x * 256 + t;
    int v = (i < NN) ? g_deg[i] : 0;
    sd[t] = v;
    __syncthreads();
    #pragma unroll
    for (int off = 1; off < 256; off <<= 1) {
        int u = (t >= off) ? sd[t - off] : 0;
        __syncthreads();
        sd[t] += u;
        __syncthreads();
    }
    if (i < NN) g_row[i] = sd[t] - v;
    if (t == 255) g_bsum[blockIdx.x] = sd[255];
}

__global__ void k_scan_top() {
    __shared__ int sd[256];
    int t = threadIdx.x;
    int v = (t < NBLK) ? g_bsum[t] : 0;
    sd[t] = v;
    __syncthreads();
    #pragma unroll
    for (int off = 1; off < 256; off <<= 1) {
        int u = (t >= off) ? sd[t - off] : 0;
        __syncthreads();
        sd[t] += u;
        __syncthreads();
    }
    if (t < NBLK) g_boff[t] = sd[t] - v;
    if (t == 255) g_row[NN] = sd[255];
}

__global__ void k_csr_fin() {
    int i = blockIdx.x * 256 + threadIdx.x;
    if (i >= NN) return;
    int r = g_row[i] + g_boff[blockIdx.x];
    g_row[i] = r;
    g_csrc[r] = i;          // self-loop slot
    g_deg[i] = r + 1;       // scatter cursor starts after self loop
}

__global__ void k_scatter(const int* __restrict__ srcp, const int* __restrict__ dstp, int E) {
    int e = blockIdx.x * blockDim.x + threadIdx.x;
    if (e >= E) return;
    int pos = atomicAdd(&g_deg[__ldg(dstp + e)], 1);
    g_csrc[pos] = __ldg(srcp + e);
}

// ---------------- GEMM1: xp1 = x @ W1  (64x64 tile, both operands in smem) ---
__global__ void k_gemm1(const float* __restrict__ x, const float* __restrict__ W1) {
    __shared__ float xs[64][72];
    __shared__ float ws[64][68];
    int t = threadIdx.x;           // 0..127
    int r0 = blockIdx.x * 64;
    int c0 = blockIdx.y * 64;
    int tr = t >> 4;               // rows [tr*8, tr*8+8)
    int tc = t & 15;               // cols [tc*4, tc*4+4)
    unsigned long long acc[4][4];
    #pragma unroll
    for (int p = 0; p < 4; p++)
        #pragma unroll
        for (int j = 0; j < 4; j++) acc[p][j] = 0ull;

    for (int k0 = 0; k0 < 128; k0 += 64) {
        __syncthreads();
        for (int i = t; i < 64 * 64; i += 128) {
            int c = i & 63, r = i >> 6;
            xs[c][r] = (r0 + r < NN) ? x[(size_t)(r0 + r) * 128 + k0 + c] : 0.f;
        }
        for (int i = t; i < 64 * 64; i += 128) {
            int c = i & 63, k = i >> 6;
            ws[k][c] = W1[(k0 + k) * 192 + c0 + c];
        }
        __syncthreads();
        #pragma unroll 4
        for (int kk = 0; kk < 64; kk++) {
            float4 wv = *(const float4*)&ws[kk][tc * 4];
            unsigned long long w0 = pk2(wv.x, wv.x), w1 = pk2(wv.y, wv.y);
            unsigned long long w2 = pk2(wv.z, wv.z), w3 = pk2(wv.w, wv.w);
            const ulonglong2* xp = (const ulonglong2*)&xs[kk][tr * 8];
            ulonglong2 q0 = xp[0], q1 = xp[1];
            fma2(acc[0][0], q0.x, w0); fma2(acc[0][1], q0.x, w1);
            fma2(acc[0][2], q0.x, w2); fma2(acc[0][3], q0.x, w3);
            fma2(acc[1][0], q0.y, w0); fma2(acc[1][1], q0.y, w1);
            fma2(acc[1][2], q0.y, w2); fma2(acc[1][3], q0.y, w3);
            fma2(acc[2][0], q1.x, w0); fma2(acc[2][1], q1.x, w1);
            fma2(acc[2][2], q1.x, w2); fma2(acc[2][3], q1.x, w3);
            fma2(acc[3][0], q1.y, w0); fma2(acc[3][1], q1.y, w1);
            fma2(acc[3][2], q1.y, w2); fma2(acc[3][3], q1.y, w3);
        }
    }
    #pragma unroll
    for (int p = 0; p < 4; p++) {
        float lo0, hi0, lo1, hi1, lo2, hi2, lo3, hi3;
        upk2(lo0, hi0, acc[p][0]); upk2(lo1, hi1, acc[p][1]);
        upk2(lo2, hi2, acc[p][2]); upk2(lo3, hi3, acc[p][3]);
        int r = r0 + tr * 8 + 2 * p;
        if (r < NN)
            *(float4*)&g_xp1[(size_t)r * 192 + c0 + tc * 4] = make_float4(lo0, lo1, lo2, lo3);
        if (r + 1 < NN)
            *(float4*)&g_xp1[(size_t)(r + 1) * 192 + c0 + tc * 4] = make_float4(hi0, hi1, hi2, hi3);
    }
}

// ---------------- fused layer1: softmax(no-max) + aggregate + bias + elu ------
// warp per dst node; 4-edge unroll for MLP (front-batched gathers)
__global__ void k_agg1(const float* __restrict__ b1) {
    int d = blockIdx.x * 8 + (threadIdx.x >> 5);
    if (d >= NN) return;
    int lane = threadIdx.x & 31;
    float ad0 = g_adst1[d * 3 + 0], ad1 = g_adst1[d * 3 + 1], ad2 = g_adst1[d * 3 + 2];
    float acc0 = 0.f, acc1 = 0.f, acc2 = 0.f, acc3 = 0.f, acc4 = 0.f, acc5 = 0.f;
    float den0 = 0.f, den1 = 0.f, den2 = 0.f;
    int beg = g_row[d], end = g_row[d + 1];
    int j = beg;
    for (; j + 4 <= end; j += 4) {
        int s[4];
        #pragma unroll
        for (int q = 0; q < 4; q++) s[q] = __ldg(g_csrc + j + q);
        float4 av[4];
        #pragma unroll
        for (int q = 0; q < 4; q++) av[q] = __ldg((const float4*)g_asrc1v + s[q]);
        float f[4][6];
        #pragma unroll
        for (int q = 0; q < 4; q++) {
            const float* xr = g_xp1 + (size_t)s[q] * 192 + lane;
            f[q][0] = __ldg(xr);       f[q][1] = __ldg(xr + 32);
            f[q][2] = __ldg(xr + 64);  f[q][3] = __ldg(xr + 96);
            f[q][4] = __ldg(xr + 128); f[q][5] = __ldg(xr + 160);
        }
        #pragma unroll
        for (int q = 0; q < 4; q++) {
            float e0 = __expf(lrelu(av[q].x + ad0));
            float e1 = __expf(lrelu(av[q].y + ad1));
            float e2 = __expf(lrelu(av[q].z + ad2));
            den0 += e0; den1 += e1; den2 += e2;
            acc0 = fmaf(e0, f[q][0], acc0); acc1 = fmaf(e0, f[q][1], acc1);
            acc2 = fmaf(e1, f[q][2], acc2); acc3 = fmaf(e1, f[q][3], acc3);
            acc4 = fmaf(e2, f[q][4], acc4); acc5 = fmaf(e2, f[q][5], acc5);
        }
    }
    for (; j < end; j++) {
        int s = __ldg(g_csrc + j);
        float4 av = __ldg((const float4*)g_asrc1v + s);
        const float* xr = g_xp1 + (size_t)s * 192 + lane;
        float e0 = __expf(lrelu(av.x + ad0));
        float e1 = __expf(lrelu(av.y + ad1));
        float e2 = __expf(lrelu(av.z + ad2));
        den0 += e0; den1 += e1; den2 += e2;
        acc0 = fmaf(e0, __ldg(xr),       acc0);
        acc1 = fmaf(e0, __ldg(xr + 32),  acc1);
        acc2 = fmaf(e1, __ldg(xr + 64),  acc2);
        acc3 = fmaf(e1, __ldg(xr + 96),  acc3);
        acc4 = fmaf(e2, __ldg(xr + 128), acc4);
        acc5 = fmaf(e2, __ldg(xr + 160), acc5);
    }
    float i0 = 1.f / fmaxf(den0, 1e-16f);
    float i1 = 1.f / fmaxf(den1, 1e-16f);
    float i2 = 1.f / fmaxf(den2, 1e-16f);
    float* o = g_h1 + (size_t)d * 192 + lane;
    float v;
    v = acc0 * i0 + b1[lane];       o[0]   = v > 0.f ? v : expm1f(v);
    v = acc1 * i0 + b1[lane + 32];  o[32]  = v > 0.f ? v : expm1f(v);
    v = acc2 * i1 + b1[lane + 64];  o[64]  = v > 0.f ? v : expm1f(v);
    v = acc3 * i1 + b1[lane + 96];  o[96]  = v > 0.f ? v : expm1f(v);
    v = acc4 * i2 + b1[lane + 128]; o[128] = v > 0.f ? v : expm1f(v);
    v = acc5 * i2 + b1[lane + 160]; o[160] = v > 0.f ? v : expm1f(v);
}

// ---------------- GEMM2 + fused att2 epilogue ---------------------------------
// Tile is full-N (64 cols), so each row's attention dots reduce across the 16
// contiguous lanes holding that row (width-16 shuffle).
__global__ void k_gemm2(const float* __restrict__ W2, const float* __restrict__ as2,
                        const float* __restrict__ ad2v) {
    __shared__ float xs[64][72];
    __shared__ float ws[64][68];
    int t = threadIdx.x;
    int r0 = blockIdx.x * 64;
    int tr = t >> 4;
    int tc = t & 15;
    unsigned long long acc[4][4];
    #pragma unroll
    for (int p = 0; p < 4; p++)
        #pragma unroll
        for (int j = 0; j < 4; j++) acc[p][j] = 0ull;

    for (int k0 = 0; k0 < 192; k0 += 64) {
        __syncthreads();
        for (int i = t; i < 64 * 64; i += 128) {
            int c = i & 63, r = i >> 6;
            xs[c][r] = (r0 + r < NN) ? g_h1[(size_t)(r0 + r) * 192 + k0 + c] : 0.f;
        }
        for (int i = t; i < 64 * 64; i += 128) {
            int c = i & 63, k = i >> 6;
            ws[k][c] = W2[(k0 + k) * 64 + c];
        }
        __syncthreads();
        #pragma unroll 4
        for (int kk = 0; kk < 64; kk++) {
            float4 wv = *(const float4*)&ws[kk][tc * 4];
            unsigned long long w0 = pk2(wv.x, wv.x), w1 = pk2(wv.y, wv.y);
            unsigned long long w2 = pk2(wv.z, wv.z), w3 = pk2(wv.w, wv.w);
            const ulonglong2* xp = (const ulonglong2*)&xs[kk][tr * 8];
            ulonglong2 q0 = xp[0], q1 = xp[1];
            fma2(acc[0][0], q0.x, w0); fma2(acc[0][1], q0.x, w1);
            fma2(acc[0][2], q0.x, w2); fma2(acc[0][3], q0.x, w3);
            fma2(acc[1][0], q0.y, w0); fma2(acc[1][1], q0.y, w1);
            fma2(acc[1][2], q0.y, w2); fma2(acc[1][3], q0.y, w3);
            fma2(acc[2][0], q1.x, w0); fma2(acc[2][1], q1.x, w1);
            fma2(acc[2][2], q1.x, w2); fma2(acc[2][3], q1.x, w3);
            fma2(acc[3][0], q1.y, w0); fma2(acc[3][1], q1.y, w1);
            fma2(acc[3][2], q1.y, w2); fma2(acc[3][3], q1.y, w3);
        }
    }

    float4 a_s = *(const float4*)&as2[tc * 4];
    float4 a_d = *(const float4*)&ad2v[tc * 4];
    #pragma unroll
    for (int p = 0; p < 4; p++) {
        float lo0, hi0, lo1, hi1, lo2, hi2, lo3, hi3;
        upk2(lo0, hi0, acc[p][0]); upk2(lo1, hi1, acc[p][1]);
        upk2(lo2, hi2, acc[p][2]); upk2(lo3, hi3, acc[p][3]);
        int r = r0 + tr * 8 + 2 * p;
        float psL = lo0 * a_s.x + lo1 * a_s.y + lo2 * a_s.z + lo3 * a_s.w;
        float pdL = lo0 * a_d.x + lo1 * a_d.y + lo2 * a_d.z + lo3 * a_d.w;
        float psH = hi0 * a_s.x + hi1 * a_s.y + hi2 * a_s.z + hi3 * a_s.w;
        float pdH = hi0 * a_d.x + hi1 * a_d.y + hi2 * a_d.z + hi3 * a_d.w;
        #pragma unroll
        for (int off = 8; off; off >>= 1) {
            psL += __shfl_xor_sync(0xFFFFFFFFu, psL, off, 16);
            pdL += __shfl_xor_sync(0xFFFFFFFFu, pdL, off, 16);
            psH += __shfl_xor_sync(0xFFFFFFFFu, psH, off, 16);
            pdH += __shfl_xor_sync(0xFFFFFFFFu, pdH, off, 16);
        }
        if (r < NN) {
            *(float4*)&g_xp2[(size_t)r * 64 + tc * 4] = make_float4(lo0, lo1, lo2, lo3);
            if (tc == 0) { g_asrc2[r] = psL; g_adst2[r] = pdL; }
        }
        if (r + 1 < NN) {
            *(float4*)&g_xp2[(size_t)(r + 1) * 64 + tc * 4] = make_float4(hi0, hi1, hi2, hi3);
            if (tc == 0) { g_asrc2[r + 1] = psH; g_adst2[r + 1] = pdH; }
        }
    }
}

// ---------------- fused layer2: softmax + aggregate + bias + pool -------------
__global__ void k_agg2(const float* __restrict__ b2, const int* __restrict__ batch) {
    int d = blockIdx.x * 8 + (threadIdx.x >> 5);
    if (d >= NN) return;
    int lane = threadIdx.x & 31;
    float ad = g_adst2[d];
    float acc0 = 0.f, acc1 = 0.f, den = 0.f;
    int beg = g_row[d], end = g_row[d + 1];
    int j = beg;
    for (; j + 4 <= end; j += 4) {
        int s[4];
        #pragma unroll
        for (int q = 0; q < 4; q++) s[q] = __ldg(g_csrc + j + q);
        float a[4], f0[4], f1[4];
        #pragma unroll
        for (int q = 0; q < 4; q++) {
            a[q] = __ldg(g_asrc2 + s[q]);
            const float* xr = g_xp2 + (size_t)s[q] * 64 + lane;
            f0[q] = __ldg(xr); f1[q] = __ldg(xr + 32);
        }
        #pragma unroll
        for (int q = 0; q < 4; q++) {
            float e = __expf(lrelu(a[q] + ad));
            den += e;
            acc0 = fmaf(e, f0[q], acc0); acc1 = fmaf(e, f1[q], acc1);
        }
    }
    for (; j < end; j++) {
        int s = __ldg(g_csrc + j);
        float e = __expf(lrelu(__ldg(g_asrc2 + s) + ad));
        den += e;
        const float* xr = g_xp2 + (size_t)s * 64 + lane;
        acc0 = fmaf(e, __ldg(xr),      acc0);
        acc1 = fmaf(e, __ldg(xr + 32), acc1);
    }
    float inv = 1.f / fmaxf(den, 1e-16f);
    int b = __ldg(batch + d);
    atomicAdd(&g_pool[b * 64 + lane],      acc0 * inv + b2[lane]);
    atomicAdd(&g_pool[b * 64 + lane + 32], acc1 * inv + b2[lane + 32]);
    if (lane == 0) atomicAdd(&g_cnt[b], 1.0f);
}

// ---------------- final: (pool/cnt) @ lin_W + lin_b ---------------------------
__global__ void k_final(const float* __restrict__ lin_W, const float* __restrict__ lin_b,
                        float* __restrict__ out) {
    int t = blockIdx.x * blockDim.x + threadIdx.x;
    if (t >= NG * 10) return;
    int g = t / 10, j = t % 10;
    float inv = 1.0f / fmaxf(g_cnt[g], 1.0f);
    float acc = lin_b[j];
    #pragma unroll 8
    for (int c = 0; c < 64; c++)
        acc += g_pool[g * 64 + c] * inv * lin_W[c * 10 + j];
    out[t] = acc;
}

// ---------------- host launch -------------------------------------------------
extern "C" void kernel_launch(void* const* d_in, const int* in_sizes, int n_in,
                              void* d_out, int out_size) {
    const float* x        = (const float*)d_in[0];
    const int*   ei       = (const int*)  d_in[1];
    const int*   batch    = (const int*)  d_in[2];
    const float* W1       = (const float*)d_in[3];
    const float* att_src1 = (const float*)d_in[4];
    const float* att_dst1 = (const float*)d_in[5];
    const float* b1       = (const float*)d_in[6];
    const float* W2       = (const float*)d_in[7];
    const float* att_src2 = (const float*)d_in[8];
    const float* att_dst2 = (const float*)d_in[9];
    const float* b2       = (const float*)d_in[10];
    const float* lin_W    = (const float*)d_in[11];
    const float* lin_b    = (const float*)d_in[12];
    float* out = (float*)d_out;

    int E = in_sizes[1] / 2;            // 800000
    const int* srcp = ei;
    const int* dstp = ei + E;

    cudaStream_t s1;
    cudaStreamCreate(&s1);
    cudaEvent_t evF, evJ;
    cudaEventCreateWithFlags(&evF, cudaEventDisableTiming);
    cudaEventCreateWithFlags(&evJ, cudaEventDisableTiming);

    k_init<<<(NN + 255) / 256, 256>>>();                        // L0 (s0)
    cudaEventRecord(evF, 0);
    cudaStreamWaitEvent(s1, evF, 0);

    k_prep_u<<<3, 128, 0, s1>>>(W1, att_src1, att_dst1);        // L1 (s1)
    k_hist<<<(E + 255) / 256, 256, 0, s1>>>(dstp, E);           // L2 (s1)
    k_gemm1<<<dim3((NN + 63) / 64, 3), 128>>>(x, W1);           // L3 (s0) PROFILED
    k_att1x<<<(NN + 7) / 8, 256, 0, s1>>>(x);                   // L4 (s1)
    k_scan_blk<<<NBLK, 256, 0, s1>>>();                         // L5 (s1)
    k_scan_top<<<1, 256, 0, s1>>>();                            // L6 (s1)
    k_csr_fin<<<NBLK, 256, 0, s1>>>();                          // L7 (s1)
    k_scatter<<<(E + 255) / 256, 256, 0, s1>>>(srcp, dstp, E);  // L8 (s1)

    cudaEventRecord(evJ, s1);
    cudaStreamWaitEvent(0, evJ, 0);

    // layer 1 aggregation, layer 2 linear (+fused att2), layer 2 aggregation
    k_agg1<<<(NN + 7) / 8, 256>>>(b1);
    k_gemm2<<<(NN + 63) / 64, 128>>>(W2, att_src2, att_dst2);
    k_agg2<<<(NN + 7) / 8, 256>>>(b2, batch);
    k_final<<<10, 128>>>(lin_W, lin_b, out);

    cudaEventDestroy(evF);
    cudaEventDestroy(evJ);
    cudaStreamDestroy(s1);
}